// round 6
// baseline (speedup 1.0000x reference)
#include <cuda_runtime.h>

// GHM loss — single fused kernel, one pass over x/target (268 MB).
// Per element: g=|x-t|, bin=floor(g*9.9999), loss=BCE(x,t) in log2 units.
// HOT LOOP IS MEMORY-CHAIN-FREE: 10 per-thread REGISTER accumulators with
// predicated adds (no smem RMW -> no data-dependent-address serialization).
// Count and loss share one fp32 accumulator per (thread,bin):
//   v += K - nl2, K=16384 -> v = count*K + loss2_sum (count<=32, |loss2|<=426)
// count recovered exactly per-thread via rintf(v/K) BEFORE reduction.
// Warp shuffle-reduce -> spread global double atomics -> last block finalizes.

#define BINS   10
#define TPB    256
#define BLOCKS 4096
#define ITERS  8                      // 4096*256*8 float4s = 2^23 exactly
#define NCOPY  32
#define NTOT   (16384LL * 2048LL)
#define KOFF   16384.0f

__device__ double             g_ls[NCOPY][BINS];   // zero-init at module load
__device__ unsigned long long g_cs[NCOPY][BINS];
__device__ unsigned int       g_done;

__global__ void __launch_bounds__(TPB, 6) ghm_kernel(
    const float4* __restrict__ x4,
    const float4* __restrict__ t4,
    float* __restrict__ out)
{
    __shared__ double s_ls[BINS], s_cs[BINS];
    __shared__ int s_last;

    const int tid = threadIdx.x;

    float acc[BINS];
#pragma unroll
    for (int b = 0; b < BINS; b++) acc[b] = 0.0f;

    const int stride = TPB * BLOCKS;
    int idx = blockIdx.x * TPB + tid;

#pragma unroll
    for (int it = 0; it < ITERS; it++, idx += stride) {
        float4 xv = __ldcs(&x4[idx]);
        float4 tv = __ldcs(&t4[idx]);
        float xs[4] = {xv.x, xv.y, xv.z, xv.w};
        float ts[4] = {tv.x, tv.y, tv.z, tv.w};
#pragma unroll
        for (int c = 0; c < 4; c++) {
            float xx  = xs[c];
            float tt  = ts[c];
            float g   = fabsf(xx - tt);
            int   bin = (int)(g * 9.9999f);          // g < 1 -> bin in [0,9]
            float a   = __log2f(xx);
            float b2  = __log2f(1.0f - xx);
            float add = fmaf(tt, b2 - a, KOFF - b2); // K - (-loss/ln2)
#pragma unroll
            for (int b = 0; b < BINS; b++)
                if (bin == b) acc[b] += add;
        }
    }

    // per-thread split (exact count, small loss residual), then warp reduce
    const int lid = tid & 31;
    const int cp  = blockIdx.x & (NCOPY - 1);
#pragma unroll
    for (int b = 0; b < BINS; b++) {
        float v  = acc[b];
        int   ci = __float2int_rn(v * (1.0f / KOFF));
        float ls = v - (float)ci * KOFF;
#pragma unroll
        for (int o = 16; o > 0; o >>= 1) {
            ls += __shfl_down_sync(0xffffffffu, ls, o);
            ci += __shfl_down_sync(0xffffffffu, ci, o);
        }
        if (lid == 0) {
            atomicAdd(&g_ls[cp][b], (double)ls);
            atomicAdd(&g_cs[cp][b], (unsigned long long)ci);
        }
    }

    // ---- last-block finalize ----
    if (tid == 0) {
        __threadfence();
        unsigned old = atomicAdd(&g_done, 1u);
        s_last = (old == (unsigned)(BLOCKS - 1)) ? 1 : 0;
    }
    __syncthreads();
    if (!s_last) return;

    if (tid < BINS) {
        double a = 0.0;
        unsigned long long c = 0ull;
#pragma unroll
        for (int k = 0; k < NCOPY; k++) {
            a += ((volatile double*)&g_ls[k][tid])[0];
            c += ((volatile unsigned long long*)&g_cs[k][tid])[0];
        }
        s_ls[tid] = a;
        s_cs[tid] = (double)c;
    }
    __syncthreads();

    if (tid == 0) {
        const double N = (double)NTOT;
        int ne = 0;
#pragma unroll
        for (int b = 0; b < BINS; b++) ne += (s_cs[b] > 0.0) ? 1 : 0;
        double tot = 0.0;
#pragma unroll
        for (int b = 0; b < BINS; b++) {
            double gd = s_cs[b] * (double)ne;
            if (gd < 1.0) gd = 1.0;
            tot += s_ls[b] * (N / gd);
        }
        out[0] = (float)(tot * 0.6931471805599453 / N);   // log2 -> ln
    }
    __syncthreads();   // reads of g_ls/g_cs complete before reset

    for (int i = tid; i < NCOPY * BINS; i += TPB) {
        g_ls[i / BINS][i % BINS] = 0.0;
        g_cs[i / BINS][i % BINS] = 0ull;
    }
    if (tid == 0) g_done = 0u;
}

extern "C" void kernel_launch(void* const* d_in, const int* in_sizes, int n_in,
                              void* d_out, int out_size)
{
    const float4* x4 = (const float4*)d_in[0];
    const float4* t4 = (const float4*)d_in[1];
    float* out = (float*)d_out;

    ghm_kernel<<<BLOCKS, TPB>>>(x4, t4, out);
}

// round 7
// speedup vs baseline: 4.1528x; 4.1528x over previous
#include <cuda_runtime.h>

// GHM loss — single fused kernel, one pass over x/target (268 MB).
// R7: MLP-first. Each outer iter front-batches 8 LDG.128 (4 float4 pairs,
// 32 buffer regs) -> ~8 loads in flight per warp. Dual smem histograms
// (even/odd element) let ptxas overlap the LDS->FADD->STS RMW chains.
// Count and loss share one fp32 accumulator per (thread,bin):
//   v += K - nl2, K=16384 -> v = count*K + loss2_sum (count<=32, |loss2|<=426)
// count recovered exactly via rintf(v/K) at reduction time.
// Last block (threadfence + counter) finalizes beta, writes mean, resets state.

#define BINS   10
#define TPB    256
#define BLOCKS 4096
#define PAIRS  4                      // float4-pairs per outer iteration
#define OUTER  2                      // 4096*256*4*2 float4s = 2^23 exactly
#define NCOPY  32
#define NTOT   (16384LL * 2048LL)
#define KOFF   16384.0f

__device__ double             g_ls[NCOPY][BINS];   // zero-init at module load
__device__ unsigned long long g_cs[NCOPY][BINS];
__device__ unsigned int       g_done;

__device__ __forceinline__ void proc(float xx, float tt, float* __restrict__ h)
{
    float g   = fabsf(xx - tt);
    int   bin = (int)(g * 9.9999f);          // g < 1 -> bin in [0,9]
    float a   = __log2f(xx);
    float b2  = __log2f(1.0f - xx);
    float add = fmaf(tt, b2 - a, KOFF - b2); // K - (-loss/ln2)
    h[bin * TPB] += add;
}

__global__ void __launch_bounds__(TPB, 5) ghm_kernel(
    const float4* __restrict__ x4,
    const float4* __restrict__ t4,
    float* __restrict__ out)
{
    __shared__ float histA[BINS * TPB];           // 10 KB
    __shared__ float histB[BINS * TPB];           // 10 KB
    __shared__ double s_ls[BINS], s_cs[BINS];
    __shared__ int s_last;

    const int tid = threadIdx.x;
    float* __restrict__ hA = &histA[tid];
    float* __restrict__ hB = &histB[tid];

#pragma unroll
    for (int b = 0; b < BINS; b++) { hA[b * TPB] = 0.0f; hB[b * TPB] = 0.0f; }
    __syncthreads();

    const int stride = TPB * BLOCKS;
    int idx = blockIdx.x * TPB + tid;

#pragma unroll
    for (int o = 0; o < OUTER; o++) {
        float4 xs[PAIRS], ts[PAIRS];
#pragma unroll
        for (int p = 0; p < PAIRS; p++) xs[p] = __ldcs(&x4[idx + p * stride]);
#pragma unroll
        for (int p = 0; p < PAIRS; p++) ts[p] = __ldcs(&t4[idx + p * stride]);
#pragma unroll
        for (int p = 0; p < PAIRS; p++) {
            proc(xs[p].x, ts[p].x, hA);
            proc(xs[p].y, ts[p].y, hB);
            proc(xs[p].z, ts[p].z, hA);
            proc(xs[p].w, ts[p].w, hB);
        }
        idx += PAIRS * stride;
    }
    __syncthreads();

    // block reduction: warp w handles bins w and w+8
    const int wid = tid >> 5;
    const int lid = tid & 31;
    const int cp  = blockIdx.x & (NCOPY - 1);
    for (int bin = wid; bin < BINS; bin += 8) {
        float ls = 0.0f;
        int   c  = 0;
#pragma unroll
        for (int k = 0; k < TPB / 32; k++) {
            float v  = histA[bin * TPB + k * 32 + lid]
                     + histB[bin * TPB + k * 32 + lid];
            int   ci = __float2int_rn(v * (1.0f / KOFF));
            ls += v - (float)ci * KOFF;
            c  += ci;
        }
#pragma unroll
        for (int o = 16; o > 0; o >>= 1) {
            ls += __shfl_down_sync(0xffffffffu, ls, o);
            c  += __shfl_down_sync(0xffffffffu, c, o);
        }
        if (lid == 0) {
            atomicAdd(&g_ls[cp][bin], (double)ls);
            atomicAdd(&g_cs[cp][bin], (unsigned long long)c);
        }
    }

    // ---- last-block finalize ----
    if (tid == 0) {
        __threadfence();
        unsigned old = atomicAdd(&g_done, 1u);
        s_last = (old == (unsigned)(BLOCKS - 1)) ? 1 : 0;
    }
    __syncthreads();
    if (!s_last) return;

    if (tid < BINS) {
        double a = 0.0;
        unsigned long long c = 0ull;
#pragma unroll
        for (int k = 0; k < NCOPY; k++) {
            a += ((volatile double*)&g_ls[k][tid])[0];
            c += ((volatile unsigned long long*)&g_cs[k][tid])[0];
        }
        s_ls[tid] = a;
        s_cs[tid] = (double)c;
    }
    __syncthreads();

    if (tid == 0) {
        const double N = (double)NTOT;
        int ne = 0;
#pragma unroll
        for (int b = 0; b < BINS; b++) ne += (s_cs[b] > 0.0) ? 1 : 0;
        double tot = 0.0;
#pragma unroll
        for (int b = 0; b < BINS; b++) {
            double gd = s_cs[b] * (double)ne;
            if (gd < 1.0) gd = 1.0;
            tot += s_ls[b] * (N / gd);
        }
        out[0] = (float)(tot * 0.6931471805599453 / N);   // log2 -> ln
    }
    __syncthreads();   // reads of g_ls/g_cs complete before reset

    for (int i = tid; i < NCOPY * BINS; i += TPB) {
        g_ls[i / BINS][i % BINS] = 0.0;
        g_cs[i / BINS][i % BINS] = 0ull;
    }
    if (tid == 0) g_done = 0u;
}

extern "C" void kernel_launch(void* const* d_in, const int* in_sizes, int n_in,
                              void* d_out, int out_size)
{
    const float4* x4 = (const float4*)d_in[0];
    const float4* t4 = (const float4*)d_in[1];
    float* out = (float*)d_out;

    ghm_kernel<<<BLOCKS, TPB>>>(x4, t4, out);
}

// round 10
// speedup vs baseline: 4.4562x; 1.0731x over previous
#include <cuda_runtime.h>

// GHM loss — single fused kernel, one pass over x/target (268 MB).
// R9 = R4 base (best: single transposed smem hist, 8 blocks/SM, regs<=32,
// no manual prefetch) + RZ-FMA bin extraction:
//   bin = lowbits( __fmaf_rz(g, 9.9999f, 2^23) )   // RZ == floor for g>=0
// One FFMA.RZ + one LOP replaces FMUL+F2I, removing the F2I from the
// quarter-rate XU pipe (which the 2 irreducible LG2s already saturate).
// NOTE: previous round's 12582911.5f magic was unrepresentable in fp32 and
// would have computed round() not floor() — corrected here via explicit RZ.
// Count and loss share one fp32 accumulator per (thread,bin):
//   v += K - nl2, K=16384 -> v = count*K + loss2_sum (count<=32, |loss2|<=426)
// count recovered exactly via rintf(v/K) at reduction time.
// Last block (threadfence + counter) finalizes beta, writes mean, resets state.

#define BINS   10
#define TPB    256
#define BLOCKS 4096
#define ITERS  8                      // 4096*256*8 float4s = 2^23 exactly
#define NCOPY  32
#define NTOT   (16384LL * 2048LL)
#define KOFF   16384.0f
#define MAGIC  8388608.0f             // 2^23; RZ-FMA -> 2^23 + floor(g*9.9999)

__device__ double             g_ls[NCOPY][BINS];   // zero-init at module load
__device__ unsigned long long g_cs[NCOPY][BINS];
__device__ unsigned int       g_done;

__device__ __forceinline__ void proc(float xx, float tt, float* __restrict__ h)
{
    float g   = fabsf(xx - tt);
    // RZ rounding truncates the exact sum toward zero; ulp=1 at 2^23, so the
    // low bits are exactly floor(g*9.9999) for g in [0,1).
    int   bin = __float_as_int(__fmaf_rz(g, 9.9999f, MAGIC)) & 15;
    float a   = __log2f(xx);
    float b2  = __log2f(1.0f - xx);
    float add = fmaf(tt, b2 - a, KOFF - b2);   // K - (-loss/ln2)
    h[bin * TPB] += add;
}

__global__ void __launch_bounds__(TPB, 8) ghm_kernel(
    const float4* __restrict__ x4,
    const float4* __restrict__ t4,
    float* __restrict__ out)
{
    __shared__ float hist[BINS * TPB];            // 10 KB
    __shared__ double s_ls[BINS], s_cs[BINS];
    __shared__ int s_last;

    const int tid = threadIdx.x;
    float* __restrict__ h = &hist[tid];

#pragma unroll
    for (int b = 0; b < BINS; b++) h[b * TPB] = 0.0f;
    __syncthreads();

    const int stride = TPB * BLOCKS;
    int idx = blockIdx.x * TPB + tid;

#pragma unroll
    for (int it = 0; it < ITERS; it++, idx += stride) {
        float4 xv = __ldcs(&x4[idx]);
        float4 tv = __ldcs(&t4[idx]);
        proc(xv.x, tv.x, h);
        proc(xv.y, tv.y, h);
        proc(xv.z, tv.z, h);
        proc(xv.w, tv.w, h);
    }
    __syncthreads();

    // block reduction: warp w handles bins w and w+8
    const int wid = tid >> 5;
    const int lid = tid & 31;
    const int cp  = blockIdx.x & (NCOPY - 1);
    for (int bin = wid; bin < BINS; bin += 8) {
        float ls = 0.0f;
        int   c  = 0;
#pragma unroll
        for (int k = 0; k < TPB / 32; k++) {
            float v  = hist[bin * TPB + k * 32 + lid];
            int   ci = __float2int_rn(v * (1.0f / KOFF));
            ls += v - (float)ci * KOFF;
            c  += ci;
        }
#pragma unroll
        for (int o = 16; o > 0; o >>= 1) {
            ls += __shfl_down_sync(0xffffffffu, ls, o);
            c  += __shfl_down_sync(0xffffffffu, c, o);
        }
        if (lid == 0) {
            atomicAdd(&g_ls[cp][bin], (double)ls);
            atomicAdd(&g_cs[cp][bin], (unsigned long long)c);
        }
    }

    // ---- last-block finalize ----
    if (tid == 0) {
        __threadfence();
        unsigned old = atomicAdd(&g_done, 1u);
        s_last = (old == (unsigned)(BLOCKS - 1)) ? 1 : 0;
    }
    __syncthreads();
    if (!s_last) return;

    if (tid < BINS) {
        double a = 0.0;
        unsigned long long c = 0ull;
#pragma unroll
        for (int k = 0; k < NCOPY; k++) {
            a += ((volatile double*)&g_ls[k][tid])[0];
            c += ((volatile unsigned long long*)&g_cs[k][tid])[0];
        }
        s_ls[tid] = a;
        s_cs[tid] = (double)c;
    }
    __syncthreads();

    if (tid == 0) {
        const double N = (double)NTOT;
        int ne = 0;
#pragma unroll
        for (int b = 0; b < BINS; b++) ne += (s_cs[b] > 0.0) ? 1 : 0;
        double tot = 0.0;
#pragma unroll
        for (int b = 0; b < BINS; b++) {
            double gd = s_cs[b] * (double)ne;
            if (gd < 1.0) gd = 1.0;
            tot += s_ls[b] * (N / gd);
        }
        out[0] = (float)(tot * 0.6931471805599453 / N);   // log2 -> ln
    }
    __syncthreads();   // reads of g_ls/g_cs complete before reset

    for (int i = tid; i < NCOPY * BINS; i += TPB) {
        g_ls[i / BINS][i % BINS] = 0.0;
        g_cs[i / BINS][i % BINS] = 0ull;
    }
    if (tid == 0) g_done = 0u;
}

extern "C" void kernel_launch(void* const* d_in, const int* in_sizes, int n_in,
                              void* d_out, int out_size)
{
    const float4* x4 = (const float4*)d_in[0];
    const float4* t4 = (const float4*)d_in[1];
    float* out = (float*)d_out;

    ghm_kernel<<<BLOCKS, TPB>>>(x4, t4, out);
}

// round 11
// speedup vs baseline: 4.7560x; 1.0673x over previous
#include <cuda_runtime.h>

// GHM loss — single fused kernel, one pass over x/target (268 MB).
// R11 = R9 + PERSISTENT GRID: exactly 148*8 = 1184 blocks (one full wave at
// occupancy 8) with a grid-stride loop. The old 4096-block launch ran 3.46
// waves -> rounded to 4 rigid waves -> 13.5% of runtime at partial fill.
// One wave removes the quantization entirely (residual imbalance ~1%:
// threads do 27 or 28 iterations; per-thread-bin count <= 28 < 32 so the
// K-offset encoding still holds).
// Bin: RZ-FMA trick (FFMA.RZ+LOP, keeps F2I off the MUFU pipe).
// Count and loss share one fp32 accumulator per (thread,bin):
//   v += K - nl2, K=16384 -> v = count*K + loss2_sum; count = rintf(v/K).
// Last block (threadfence + counter) finalizes beta, writes mean, resets state.

#define BINS   10
#define TPB    256
#define BLOCKS (148 * 8)              // 1184 = one full wave at 8 blocks/SM
#define N4TOT  8388608                // 2^23 float4s per tensor
#define NCOPY  32
#define NTOT   (16384LL * 2048LL)
#define KOFF   16384.0f
#define MAGIC  8388608.0f             // 2^23; RZ-FMA -> 2^23 + floor(g*9.9999)

__device__ double             g_ls[NCOPY][BINS];   // zero-init at module load
__device__ unsigned long long g_cs[NCOPY][BINS];
__device__ unsigned int       g_done;

__device__ __forceinline__ void proc(float xx, float tt, float* __restrict__ h)
{
    float g   = fabsf(xx - tt);
    // RZ-FMA truncates toward zero; ulp=1 at 2^23 -> low bits = floor(g*9.9999)
    int   bin = __float_as_int(__fmaf_rz(g, 9.9999f, MAGIC)) & 15;
    float a   = __log2f(xx);
    float b2  = __log2f(1.0f - xx);
    float add = fmaf(tt, b2 - a, KOFF - b2);   // K - (-loss/ln2)
    h[bin * TPB] += add;
}

__global__ void __launch_bounds__(TPB, 8) ghm_kernel(
    const float4* __restrict__ x4,
    const float4* __restrict__ t4,
    float* __restrict__ out)
{
    __shared__ float hist[BINS * TPB];            // 10 KB
    __shared__ double s_ls[BINS], s_cs[BINS];
    __shared__ int s_last;

    const int tid = threadIdx.x;
    float* __restrict__ h = &hist[tid];

#pragma unroll
    for (int b = 0; b < BINS; b++) h[b * TPB] = 0.0f;
    __syncthreads();

    const int stride = TPB * BLOCKS;              // 303104
    for (int idx = blockIdx.x * TPB + tid; idx < N4TOT; idx += stride) {
        float4 xv = __ldcs(&x4[idx]);
        float4 tv = __ldcs(&t4[idx]);
        proc(xv.x, tv.x, h);
        proc(xv.y, tv.y, h);
        proc(xv.z, tv.z, h);
        proc(xv.w, tv.w, h);
    }
    __syncthreads();

    // block reduction: warp w handles bins w and w+8
    const int wid = tid >> 5;
    const int lid = tid & 31;
    const int cp  = blockIdx.x & (NCOPY - 1);
    for (int bin = wid; bin < BINS; bin += 8) {
        float ls = 0.0f;
        int   c  = 0;
#pragma unroll
        for (int k = 0; k < TPB / 32; k++) {
            float v  = hist[bin * TPB + k * 32 + lid];
            int   ci = __float2int_rn(v * (1.0f / KOFF));
            ls += v - (float)ci * KOFF;
            c  += ci;
        }
#pragma unroll
        for (int o = 16; o > 0; o >>= 1) {
            ls += __shfl_down_sync(0xffffffffu, ls, o);
            c  += __shfl_down_sync(0xffffffffu, c, o);
        }
        if (lid == 0) {
            atomicAdd(&g_ls[cp][bin], (double)ls);
            atomicAdd(&g_cs[cp][bin], (unsigned long long)c);
        }
    }

    // ---- last-block finalize ----
    if (tid == 0) {
        __threadfence();
        unsigned old = atomicAdd(&g_done, 1u);
        s_last = (old == (unsigned)(BLOCKS - 1)) ? 1 : 0;
    }
    __syncthreads();
    if (!s_last) return;

    if (tid < BINS) {
        double a = 0.0;
        unsigned long long c = 0ull;
#pragma unroll
        for (int k = 0; k < NCOPY; k++) {
            a += ((volatile double*)&g_ls[k][tid])[0];
            c += ((volatile unsigned long long*)&g_cs[k][tid])[0];
        }
        s_ls[tid] = a;
        s_cs[tid] = (double)c;
    }
    __syncthreads();

    if (tid == 0) {
        const double N = (double)NTOT;
        int ne = 0;
#pragma unroll
        for (int b = 0; b < BINS; b++) ne += (s_cs[b] > 0.0) ? 1 : 0;
        double tot = 0.0;
#pragma unroll
        for (int b = 0; b < BINS; b++) {
            double gd = s_cs[b] * (double)ne;
            if (gd < 1.0) gd = 1.0;
            tot += s_ls[b] * (N / gd);
        }
        out[0] = (float)(tot * 0.6931471805599453 / N);   // log2 -> ln
    }
    __syncthreads();   // reads of g_ls/g_cs complete before reset

    for (int i = tid; i < NCOPY * BINS; i += TPB) {
        g_ls[i / BINS][i % BINS] = 0.0;
        g_cs[i / BINS][i % BINS] = 0ull;
    }
    if (tid == 0) g_done = 0u;
}

extern "C" void kernel_launch(void* const* d_in, const int* in_sizes, int n_in,
                              void* d_out, int out_size)
{
    const float4* x4 = (const float4*)d_in[0];
    const float4* t4 = (const float4*)d_in[1];
    float* out = (float*)d_out;

    ghm_kernel<<<BLOCKS, TPB>>>(x4, t4, out);
}